// round 4
// baseline (speedup 1.0000x reference)
#include <cuda_runtime.h>

#define DT 0.05f
#define NSTEPS 41
#define TPB 128
#define MAXB 4096

typedef unsigned long long u64;

// partial sums: [2b] = sum(err+eff), [2b+1] = sum(nor); zero-init counter
__device__ float g_partials[2 * MAXB];
__device__ unsigned g_count;

static __device__ __forceinline__ u64 pk2(float lo, float hi) {
    u64 r; asm("mov.b64 %0, {%1, %2};" : "=l"(r) : "f"(lo), "f"(hi)); return r;
}
static __device__ __forceinline__ void up2(u64 v, float& lo, float& hi) {
    asm("mov.b64 {%0, %1}, %2;" : "=f"(lo), "=f"(hi) : "l"(v));
}
static __device__ __forceinline__ u64 bc2(float x) { return pk2(x, x); }
static __device__ __forceinline__ u64 ffma2(u64 a, u64 b, u64 c) {
    u64 d; asm("fma.rn.f32x2 %0, %1, %2, %3;" : "=l"(d) : "l"(a), "l"(b), "l"(c)); return d;
}
static __device__ __forceinline__ u64 fmul2(u64 a, u64 b) {
    u64 d; asm("mul.rn.f32x2 %0, %1, %2;" : "=l"(d) : "l"(a), "l"(b)); return d;
}

// both-lane tanh via one MUFU: f32x2 -> f16x2 -> tanh.approx.f16x2 -> 2x f32
static __device__ __forceinline__ void tanh2f(u64 x, float& lo, float& hi) {
    float xl, xh; up2(x, xl, xh);
    unsigned hp;
    asm("cvt.rn.f16x2.f32 %0, %1, %2;" : "=r"(hp) : "f"(xh), "f"(xl)); // hi half = xh
    asm("tanh.approx.f16x2 %0, %0;" : "+r"(hp));
    asm("{\n\t"
        ".reg .b16 l, h;\n\t"
        "mov.b32 {l, h}, %2;\n\t"
        "cvt.f32.f16 %0, l;\n\t"
        "cvt.f32.f16 %1, h;\n\t"
        "}" : "=f"(lo), "=f"(hi) : "r"(hp));
}
static __device__ __forceinline__ u64 tanh2(u64 x) {
    float lo, hi; tanh2f(x, lo, hi); return pk2(lo, hi);
}

__global__ void __launch_bounds__(TPB, 3) conv_fused_kernel(
    const float* __restrict__ omega,
    const float* __restrict__ Wh1, const float* __restrict__ bh1,
    const float* __restrict__ Wh2, const float* __restrict__ bh2,
    const float* __restrict__ Wr1, const float* __restrict__ br1,
    const float* __restrict__ Wr2, const float* __restrict__ br2,
    const float* __restrict__ alpha, float* __restrict__ out,
    int N, int npairs, int nblocks)
{
    // ---- hoist weights (uniform address -> L1 broadcast), broadcast-pack ----
    float whA[4], whB[4], vbh1[4];          // Wh1 cols 0,1 (loop-invariant) + bias
    u64 wh1s[8];                            // Wh1 cols 2,3 (multiply s0,s1)
    #pragma unroll
    for (int j = 0; j < 4; j++) {
        whA[j]  = __ldg(&Wh1[4 * j + 0]);
        whB[j]  = __ldg(&Wh1[4 * j + 1]);
        vbh1[j] = __ldg(&bh1[j]);
        wh1s[2 * j + 0] = bc2(__ldg(&Wh1[4 * j + 2]));
        wh1s[2 * j + 1] = bc2(__ldg(&Wh1[4 * j + 3]));
    }
    u64 wh2p[4], wr1p[9], wr2p[3], br1p[3];
    #pragma unroll
    for (int j = 0; j < 4; j++) wh2p[j] = bc2(__ldg(&Wh2[j]));
    #pragma unroll
    for (int j = 0; j < 9; j++) wr1p[j] = bc2(__ldg(&Wr1[j]));
    #pragma unroll
    for (int j = 0; j < 3; j++) { wr2p[j] = bc2(__ldg(&Wr2[j])); br1p[j] = bc2(__ldg(&br1[j])); }
    const u64 bh2p  = bc2(__ldg(&bh2[0]));
    const u64 br2p  = bc2(__ldg(&br2[0]));
    const u64 cN1   = bc2(-1.0f);
    const u64 cTEN  = bc2(10.0f);
    const u64 cP1   = bc2(0.1f);
    const u64 cDT   = bc2(DT);

    float csum = 0.0f, nsum = 0.0f;

    for (int p = blockIdx.x * TPB + threadIdx.x; p < npairs; p += nblocks * TPB) {
        const float2 t0v = *(const float2*)(omega + 2 * p);       // omega[0, 2p..2p+1]
        const float2 t1v = *(const float2*)(omega + N + 2 * p);   // omega[1, 2p..2p+1]
        const u64 t0 = pk2(t0v.x, t0v.y);
        const u64 t1 = pk2(t1v.x, t1v.y);

        // per-pair hoisted first-layer partials: hb[j] = bh1 + W[:,0]*t0 + W[:,1]*t1
        u64 hb[4];
        #pragma unroll
        for (int j = 0; j < 4; j++)
            hb[j] = ffma2(bc2(whB[j]), t1, ffma2(bc2(whA[j]), t0, bc2(vbh1[j])));

        u64 s0 = 0ull, s1 = 0ull, err = 0ull, nor = 0ull;
        float effl = 0.0f, effh = 0.0f;

        #pragma unroll 1
        for (int st = 0; st < NSTEPS - 1; st++) {
            const u64 e0 = ffma2(s0, cN1, t0);          // t0 - s0
            const u64 e1 = ffma2(s1, cN1, t1);          // t1 - s1
            err = ffma2(fmul2(e0, cTEN), e0, err);
            err = ffma2(e1, e1, err);
            const u64 zt = ffma2(cP1, e1, e0);

            // human MLP hidden (t-part prefolded into hb)
            const u64 h0 = tanh2(ffma2(wh1s[1], s1, ffma2(wh1s[0], s0, hb[0])));
            const u64 h1 = tanh2(ffma2(wh1s[3], s1, ffma2(wh1s[2], s0, hb[1])));
            const u64 h2 = tanh2(ffma2(wh1s[5], s1, ffma2(wh1s[4], s0, hb[2])));
            const u64 h3 = tanh2(ffma2(wh1s[7], s1, ffma2(wh1s[6], s0, hb[3])));

            u64 zz = ffma2(wh2p[0], h0, bh2p);
            zz = ffma2(wh2p[1], h1, zz);
            zz = ffma2(wh2p[2], h2, zz);
            zz = ffma2(wh2p[3], h3, zz);
            float zl, zh; tanh2f(zz, zl, zh);
            const u64 z = pk2(zl, zh);

            // robot MLP
            const u64 r0 = tanh2(ffma2(wr1p[2], z, ffma2(wr1p[1], s1, ffma2(wr1p[0], s0, br1p[0]))));
            const u64 r1 = tanh2(ffma2(wr1p[5], z, ffma2(wr1p[4], s1, ffma2(wr1p[3], s0, br1p[1]))));
            const u64 r2 = tanh2(ffma2(wr1p[8], z, ffma2(wr1p[7], s1, ffma2(wr1p[6], s0, br1p[2]))));

            u64 a = ffma2(wr2p[0], r0, br2p);
            a = ffma2(wr2p[1], r1, a);
            a = ffma2(wr2p[2], r2, a);

            s0 = ffma2(cDT, s1, s0);
            s1 = ffma2(cDT, a, s1);

            effl += (fabsf(zl) > 0.01f) ? 1.0f : 0.0f;
            effh += (fabsf(zh) > 0.01f) ? 1.0f : 0.0f;
            const u64 d = ffma2(z, cN1, zt);            // zt - z
            nor = ffma2(d, d, nor);
        }

        const u64 e0 = ffma2(s0, cN1, t0);
        const u64 e1 = ffma2(s1, cN1, t1);
        err = ffma2(fmul2(e0, cTEN), e0, err);
        err = ffma2(e1, e1, err);

        float erl, erh, nl, nh;
        up2(err, erl, erh); up2(nor, nl, nh);
        csum += (erl + effl) + (erh + effh);
        nsum += nl + nh;
    }

    // ---- deterministic block reduction ----
    #pragma unroll
    for (int off = 16; off > 0; off >>= 1) {
        csum += __shfl_down_sync(0xffffffffu, csum, off);
        nsum += __shfl_down_sync(0xffffffffu, nsum, off);
    }
    __shared__ float sc[TPB / 32], sn[TPB / 32];
    __shared__ int s_last;
    const int lane = threadIdx.x & 31;
    const int warp = threadIdx.x >> 5;
    if (lane == 0) { sc[warp] = csum; sn[warp] = nsum; }
    __syncthreads();
    if (threadIdx.x == 0) {
        float bc = 0.0f, bn = 0.0f;
        #pragma unroll
        for (int w = 0; w < TPB / 32; w++) { bc += sc[w]; bn += sn[w]; }
        g_partials[2 * blockIdx.x]     = bc;
        g_partials[2 * blockIdx.x + 1] = bn;
        __threadfence();
        unsigned t = atomicAdd(&g_count, 1u);
        s_last = (t == (unsigned)(nblocks - 1)) ? 1 : 0;
    }
    __syncthreads();

    if (s_last) {
        __threadfence();  // acquire all blocks' partials
        float c = 0.0f, n = 0.0f;
        for (int j = threadIdx.x; j < nblocks; j += TPB) {   // fixed order -> deterministic
            c += g_partials[2 * j];
            n += g_partials[2 * j + 1];
        }
        #pragma unroll
        for (int off = 16; off > 0; off >>= 1) {
            c += __shfl_down_sync(0xffffffffu, c, off);
            n += __shfl_down_sync(0xffffffffu, n, off);
        }
        if (lane == 0) { sc[warp] = c; sn[warp] = n; }
        __syncthreads();
        if (threadIdx.x == 0) {
            c = 0.0f; n = 0.0f;
            #pragma unroll
            for (int w = 0; w < TPB / 32; w++) { c += sc[w]; n += sn[w]; }
            const float invN = 1.0f / (float)N;
            out[0] = c * invN + alpha[0] * (n * invN);
            g_count = 0;   // reset for next graph replay
        }
    }
}

extern "C" void kernel_launch(void* const* d_in, const int* in_sizes, int n_in,
                              void* d_out, int out_size)
{
    const float* omega = (const float*)d_in[0];
    const float* Wh1   = (const float*)d_in[1];
    const float* bh1   = (const float*)d_in[2];
    const float* Wh2   = (const float*)d_in[3];
    const float* bh2   = (const float*)d_in[4];
    const float* Wr1   = (const float*)d_in[5];
    const float* br1   = (const float*)d_in[6];
    const float* Wr2   = (const float*)d_in[7];
    const float* br2   = (const float*)d_in[8];
    const float* alpha = (const float*)d_in[9];
    (void)n_in; (void)out_size;

    const int N = in_sizes[0] / 2;     // omega is [2, N]
    const int npairs = N / 2;          // N = 1048576 (even)
    int nblocks = (npairs + TPB - 1) / TPB;
    if (nblocks > MAXB) nblocks = MAXB;

    conv_fused_kernel<<<nblocks, TPB>>>(omega, Wh1, bh1, Wh2, bh2,
                                        Wr1, br1, Wr2, br2, alpha,
                                        (float*)d_out, N, npairs, nblocks);
}

// round 5
// speedup vs baseline: 1.0243x; 1.0243x over previous
#include <cuda_runtime.h>

#define DT 0.05f
#define NSTEPS 41
#define TPB 128
#define MAXB 4096

typedef unsigned long long u64;

__device__ float g_partials[2 * MAXB];
__device__ unsigned g_count;

// ---------- f32x2 helpers ----------
static __device__ __forceinline__ u64 pk2(float lo, float hi) {
    u64 r; asm("mov.b64 %0, {%1, %2};" : "=l"(r) : "f"(lo), "f"(hi)); return r;
}
static __device__ __forceinline__ void up2(u64 v, float& lo, float& hi) {
    asm("mov.b64 {%0, %1}, %2;" : "=f"(lo), "=f"(hi) : "l"(v));
}
static __device__ __forceinline__ u64 bc2(float x) { return pk2(x, x); }
static __device__ __forceinline__ u64 ffma2(u64 a, u64 b, u64 c) {
    u64 d; asm("fma.rn.f32x2 %0, %1, %2, %3;" : "=l"(d) : "l"(a), "l"(b), "l"(c)); return d;
}
static __device__ __forceinline__ u64 fadd2(u64 a, u64 b) {
    u64 d; asm("add.rn.f32x2 %0, %1, %2;" : "=l"(d) : "l"(a), "l"(b)); return d;
}

// ---------- f16x2 helpers ----------
static __device__ __forceinline__ unsigned hfma2(unsigned a, unsigned b, unsigned c) {
    unsigned d; asm("fma.rn.f16x2 %0, %1, %2, %3;" : "=r"(d) : "r"(a), "r"(b), "r"(c)); return d;
}
static __device__ __forceinline__ unsigned hmul2(unsigned a, unsigned b) {
    unsigned d; asm("mul.rn.f16x2 %0, %1, %2;" : "=r"(d) : "r"(a), "r"(b)); return d;
}
static __device__ __forceinline__ unsigned htanh2(unsigned x) {
    asm("tanh.approx.f16x2 %0, %0;" : "+r"(x)); return x;
}
// broadcast f32 scalar into both f16 halves
static __device__ __forceinline__ unsigned bch(float x) {
    unsigned r; asm("cvt.rn.f16x2.f32 %0, %1, %1;" : "=r"(r) : "f"(x)); return r;
}
// f32x2 -> f16x2 (lane-preserving: lo->lo, hi->hi)
static __device__ __forceinline__ unsigned cvt_f16x2(u64 x) {
    float lo, hi; up2(x, lo, hi);
    unsigned r; asm("cvt.rn.f16x2.f32 %0, %1, %2;" : "=r"(r) : "f"(hi), "f"(lo));
    return r;
}
// f16x2 -> two f32
static __device__ __forceinline__ void cvt_f32p(unsigned h, float& lo, float& hi) {
    asm("{\n\t.reg .b16 l, hh;\n\tmov.b32 {l, hh}, %2;\n\t"
        "cvt.f32.f16 %0, l;\n\tcvt.f32.f16 %1, hh;\n\t}"
        : "=f"(lo), "=f"(hi) : "r"(h));
}

__global__ void __launch_bounds__(TPB) conv_fused_kernel(
    const float* __restrict__ omega,
    const float* __restrict__ Wh1, const float* __restrict__ bh1,
    const float* __restrict__ Wh2, const float* __restrict__ bh2,
    const float* __restrict__ Wr1, const float* __restrict__ br1,
    const float* __restrict__ Wr2, const float* __restrict__ br2,
    const float* __restrict__ alpha, float* __restrict__ out,
    int N, int npairs, int nblocks)
{
    // ---- hoisted weights ----
    // human first layer: t-columns stay scalar f32 (prefolded per pair);
    // s-columns as f16x2 broadcast (feed HFMA2)
    float whA[4], whB[4], vbh1[4];
    unsigned wh1s[8];             // [2j]=col2(s0), [2j+1]=col3(s1)
    #pragma unroll
    for (int j = 0; j < 4; j++) {
        whA[j]  = __ldg(&Wh1[4 * j + 0]);
        whB[j]  = __ldg(&Wh1[4 * j + 1]);
        vbh1[j] = __ldg(&bh1[j]);
        wh1s[2 * j + 0] = bch(__ldg(&Wh1[4 * j + 2]));
        wh1s[2 * j + 1] = bch(__ldg(&Wh1[4 * j + 3]));
    }
    unsigned wh2h[4], wr2h[3];
    #pragma unroll
    for (int j = 0; j < 4; j++) wh2h[j] = bch(__ldg(&Wh2[j]));
    #pragma unroll
    for (int j = 0; j < 3; j++) wr2h[j] = bch(__ldg(&Wr2[j]));
    const unsigned bh2h = bch(__ldg(&bh2[0]));

    // robot hidden layer: exact f32x2 (biases exact -> no systematic dynamics drift)
    u64 wr1p[9], br1p[3];
    #pragma unroll
    for (int j = 0; j < 9; j++) wr1p[j] = bc2(__ldg(&Wr1[j]));
    #pragma unroll
    for (int j = 0; j < 3; j++) br1p[j] = bc2(__ldg(&br1[j]));
    const u64 br2p = bc2(__ldg(&br2[0]));

    const u64 cN1 = bc2(-1.0f);
    const u64 cP1 = bc2(0.1f);
    const u64 cDT = bc2(DT);

    float csum = 0.0f, nsum = 0.0f;

    for (int p = blockIdx.x * TPB + threadIdx.x; p < npairs; p += nblocks * TPB) {
        const float2 t0v = *(const float2*)(omega + 2 * p);
        const float2 t1v = *(const float2*)(omega + N + 2 * p);
        const u64 t0 = pk2(t0v.x, t0v.y);
        const u64 t1 = pk2(t1v.x, t1v.y);

        // prefold t-contributions of human layer 1 (f32, then f16x2 once per pair)
        unsigned hb16[4];
        #pragma unroll
        for (int j = 0; j < 4; j++) {
            u64 hb = ffma2(bc2(whB[j]), t1, ffma2(bc2(whA[j]), t0, bc2(vbh1[j])));
            hb16[j] = cvt_f16x2(hb);
        }

        u64 s0 = 0ull, s1 = 0ull;
        u64 err0 = 0ull, err1 = 0ull, nor = 0ull;
        float effl = 0.0f, effh = 0.0f;

        #pragma unroll 1
        for (int st = 0; st < NSTEPS - 1; st++) {
            const u64 e0 = ffma2(s0, cN1, t0);
            const u64 e1 = ffma2(s1, cN1, t1);
            err0 = ffma2(e0, e0, err0);           // x10 applied at the end
            err1 = ffma2(e1, e1, err1);
            const u64 zt = ffma2(cP1, e1, e0);

            // ---- human MLP: fully f16x2, no back-converts ----
            const unsigned s0h = cvt_f16x2(s0);
            const unsigned s1h = cvt_f16x2(s1);
            const unsigned h0 = htanh2(hfma2(wh1s[1], s1h, hfma2(wh1s[0], s0h, hb16[0])));
            const unsigned h1 = htanh2(hfma2(wh1s[3], s1h, hfma2(wh1s[2], s0h, hb16[1])));
            const unsigned h2 = htanh2(hfma2(wh1s[5], s1h, hfma2(wh1s[4], s0h, hb16[2])));
            const unsigned h3 = htanh2(hfma2(wh1s[7], s1h, hfma2(wh1s[6], s0h, hb16[3])));
            unsigned zz = hfma2(wh2h[0], h0, bh2h);
            zz = hfma2(wh2h[1], h1, zz);
            zz = hfma2(wh2h[2], h2, zz);
            zz = hfma2(wh2h[3], h3, zz);
            const unsigned zh16 = htanh2(zz);
            float zl, zhf; cvt_f32p(zh16, zl, zhf);
            const u64 zf = pk2(zl, zhf);

            // ---- robot MLP: exact f32x2 preacts, f16x2 outputs ----
            const u64 rp0 = ffma2(wr1p[2], zf, ffma2(wr1p[1], s1, ffma2(wr1p[0], s0, br1p[0])));
            const u64 rp1 = ffma2(wr1p[5], zf, ffma2(wr1p[4], s1, ffma2(wr1p[3], s0, br1p[1])));
            const u64 rp2 = ffma2(wr1p[8], zf, ffma2(wr1p[7], s1, ffma2(wr1p[6], s0, br1p[2])));
            const unsigned r0 = htanh2(cvt_f16x2(rp0));
            const unsigned r1 = htanh2(cvt_f16x2(rp1));
            const unsigned r2 = htanh2(cvt_f16x2(rp2));

            // a = br2 (exact f32) + sum of f16 products (zero-mean rounding)
            unsigned as16 = hmul2(wr2h[0], r0);
            as16 = hfma2(wr2h[1], r1, as16);
            as16 = hfma2(wr2h[2], r2, as16);
            float al, ah; cvt_f32p(as16, al, ah);
            const u64 a = fadd2(pk2(al, ah), br2p);

            s0 = ffma2(cDT, s1, s0);
            s1 = ffma2(cDT, a, s1);

            effl += (fabsf(zl) > 0.01f) ? 1.0f : 0.0f;
            effh += (fabsf(zhf) > 0.01f) ? 1.0f : 0.0f;
            const u64 d = ffma2(zf, cN1, zt);
            nor = ffma2(d, d, nor);
        }

        const u64 e0 = ffma2(s0, cN1, t0);
        const u64 e1 = ffma2(s1, cN1, t1);
        err0 = ffma2(e0, e0, err0);
        err1 = ffma2(e1, e1, err1);

        float a0, b0, a1, b1, nl, nh;
        up2(err0, a0, b0); up2(err1, a1, b1); up2(nor, nl, nh);
        csum += (fmaf(10.0f, a0, a1) + effl) + (fmaf(10.0f, b0, b1) + effh);
        nsum += nl + nh;
    }

    // ---- deterministic fused reduction ----
    #pragma unroll
    for (int off = 16; off > 0; off >>= 1) {
        csum += __shfl_down_sync(0xffffffffu, csum, off);
        nsum += __shfl_down_sync(0xffffffffu, nsum, off);
    }
    __shared__ float sc[TPB / 32], sn[TPB / 32];
    __shared__ int s_last;
    const int lane = threadIdx.x & 31;
    const int warp = threadIdx.x >> 5;
    if (lane == 0) { sc[warp] = csum; sn[warp] = nsum; }
    __syncthreads();
    if (threadIdx.x == 0) {
        float bc = 0.0f, bn = 0.0f;
        #pragma unroll
        for (int w = 0; w < TPB / 32; w++) { bc += sc[w]; bn += sn[w]; }
        g_partials[2 * blockIdx.x]     = bc;
        g_partials[2 * blockIdx.x + 1] = bn;
        __threadfence();
        unsigned t = atomicAdd(&g_count, 1u);
        s_last = (t == (unsigned)(nblocks - 1)) ? 1 : 0;
    }
    __syncthreads();

    if (s_last) {
        __threadfence();
        float c = 0.0f, n = 0.0f;
        for (int j = threadIdx.x; j < nblocks; j += TPB) {
            c += g_partials[2 * j];
            n += g_partials[2 * j + 1];
        }
        #pragma unroll
        for (int off = 16; off > 0; off >>= 1) {
            c += __shfl_down_sync(0xffffffffu, c, off);
            n += __shfl_down_sync(0xffffffffu, n, off);
        }
        if (lane == 0) { sc[warp] = c; sn[warp] = n; }
        __syncthreads();
        if (threadIdx.x == 0) {
            c = 0.0f; n = 0.0f;
            #pragma unroll
            for (int w = 0; w < TPB / 32; w++) { c += sc[w]; n += sn[w]; }
            const float invN = 1.0f / (float)N;
            out[0] = c * invN + alpha[0] * (n * invN);
            g_count = 0;  // reset for next graph replay
        }
    }
}

extern "C" void kernel_launch(void* const* d_in, const int* in_sizes, int n_in,
                              void* d_out, int out_size)
{
    const float* omega = (const float*)d_in[0];
    const float* Wh1   = (const float*)d_in[1];
    const float* bh1   = (const float*)d_in[2];
    const float* Wh2   = (const float*)d_in[3];
    const float* bh2   = (const float*)d_in[4];
    const float* Wr1   = (const float*)d_in[5];
    const float* br1   = (const float*)d_in[6];
    const float* Wr2   = (const float*)d_in[7];
    const float* br2   = (const float*)d_in[8];
    const float* alpha = (const float*)d_in[9];
    (void)n_in; (void)out_size;

    const int N = in_sizes[0] / 2;   // omega is [2, N]
    const int npairs = N / 2;
    int nblocks = (npairs + TPB - 1) / TPB;
    if (nblocks > MAXB) nblocks = MAXB;

    conv_fused_kernel<<<nblocks, TPB>>>(omega, Wh1, bh1, Wh2, bh2,
                                        Wr1, br1, Wr2, br2, alpha,
                                        (float*)d_out, N, npairs, nblocks);
}